// round 1
// baseline (speedup 1.0000x reference)
#include <cuda_runtime.h>
#include <cstdint>

#define VOCAB 100000
#define EMB   128

// Scratch: transposed (vocab-major) embedding table with bias fused in.
// 100000 * 128 * 4B = 51.2 MB — fits in GB300's ~126 MB L2.
__device__ float g_table[(size_t)VOCAB * EMB];

// ---------------------------------------------------------------------------
// Kernel 1: table[v][j] = W[j][v] + b[j]
// 32x32 shared-memory tiled transpose. Grid: (VOCAB/32, EMB/32) = (3125, 4).
// Block: (32, 8), each thread handles 4 rows of the tile.
// ---------------------------------------------------------------------------
__global__ void transpose_bias_kernel(const float* __restrict__ W,
                                      const float* __restrict__ b) {
    __shared__ float tile[32][33];  // +1 pad: conflict-free transposed reads

    const int v0 = blockIdx.x * 32;   // vocab tile origin
    const int j0 = blockIdx.y * 32;   // emb tile origin
    const int tx = threadIdx.x;       // 0..31
    const int ty = threadIdx.y;       // 0..7

    // Coalesced read from W: consecutive tx -> consecutive vocab columns
    #pragma unroll
    for (int i = 0; i < 4; i++) {
        int j = j0 + ty + i * 8;
        tile[ty + i * 8][tx] = W[(size_t)j * VOCAB + v0 + tx];
    }
    __syncthreads();

    const float bj = b[j0 + tx];
    // Coalesced write to table: consecutive tx -> consecutive emb entries
    #pragma unroll
    for (int i = 0; i < 4; i++) {
        int v = v0 + ty + i * 8;
        g_table[(size_t)v * EMB + j0 + tx] = tile[tx][ty + i * 8] + bj;
    }
}

// ---------------------------------------------------------------------------
// Kernel 2: one warp per token.
//   e = table[x[tok]]          (512B contiguous, float4 per lane)
//   out = e / max(||e||_2, 1e-12)
// ---------------------------------------------------------------------------
__global__ void gather_norm_kernel(const int* __restrict__ x,
                                   float* __restrict__ out,
                                   int n_tok) {
    const int gwarp = (blockIdx.x * blockDim.x + threadIdx.x) >> 5;
    const int lane  = threadIdx.x & 31;
    if (gwarp >= n_tok) return;

    const int idx = __ldg(&x[gwarp]);   // uniform across warp (broadcast)

    const float4* row = reinterpret_cast<const float4*>(g_table + (size_t)idx * EMB);
    float4 v = __ldg(&row[lane]);

    float s = v.x * v.x + v.y * v.y + v.z * v.z + v.w * v.w;
    #pragma unroll
    for (int o = 16; o > 0; o >>= 1)
        s += __shfl_xor_sync(0xFFFFFFFFu, s, o);

    const float inv = 1.0f / fmaxf(sqrtf(s), 1e-12f);
    float4 r;
    r.x = v.x * inv; r.y = v.y * inv; r.z = v.z * inv; r.w = v.w * inv;

    reinterpret_cast<float4*>(out + (size_t)gwarp * EMB)[lane] = r;
}

// ---------------------------------------------------------------------------
// Launch: transpose (re-run every call — deterministic, graph-capturable),
// then the gather/normalize pass.
// ---------------------------------------------------------------------------
extern "C" void kernel_launch(void* const* d_in, const int* in_sizes, int n_in,
                              void* d_out, int out_size) {
    const int*   x = (const int*)d_in[0];    // [4096, 200] int32
    const float* W = (const float*)d_in[1];  // [128, 100000] fp32
    const float* b = (const float*)d_in[2];  // [128] fp32
    float* out = (float*)d_out;              // [4096, 200, 128] fp32

    const int n_tok = in_sizes[0];           // 819200

    dim3 tb(32, 8);
    dim3 tg(VOCAB / 32, EMB / 32);           // (3125, 4)
    transpose_bias_kernel<<<tg, tb>>>(W, b);

    const int threads = 256;                 // 8 warps/block = 8 tokens/block
    const int warps_per_block = threads / 32;
    const int blocks = (n_tok + warps_per_block - 1) / warps_per_block;
    gather_norm_kernel<<<blocks, threads>>>(x, out, n_tok);
}

// round 2
// speedup vs baseline: 1.6534x; 1.6534x over previous
#include <cuda_runtime.h>
#include <cstdint>

#define VOCAB 100000
#define EMB   128

// Scratch: vocab-major, bias-fused, L2-NORMALIZED embedding table.
// 100000 * 128 * 4B = 51.2 MB — fits in GB300's ~126 MB L2.
__device__ float g_table[(size_t)VOCAB * EMB];

// ---------------------------------------------------------------------------
// Kernel 1: table[v][:] = normalize(W[:, v] + b)
// One block per 32 vocab entries. Block = 256 threads.
//  - Load 128(j) x 32(v) tile of W into smem (coalesced over v), fusing +b.
//  - 8 warps x 4 vocab rows each: shuffle-reduce sum of squares, scale, and
//    write the 128-float normalized row coalesced.
// ---------------------------------------------------------------------------
__global__ __launch_bounds__(256) void build_table_kernel(
        const float* __restrict__ W,
        const float* __restrict__ b) {
    __shared__ float tile[EMB][33];   // [j][v_local], pad -> conflict-free

    const int v0   = blockIdx.x * 32;
    const int tid  = threadIdx.x;
    const int lane = tid & 31;
    const int wid  = tid >> 5;        // 0..7

    // Load + bias: 4096 elements, 16 per thread. Warp reads one j-row of 32
    // consecutive vocab columns = one 128B line.
    #pragma unroll
    for (int k = 0; k < 16; k++) {
        int j = k * 8 + wid;
        tile[j][lane] = W[(size_t)j * VOCAB + v0 + lane] + b[j];
    }
    __syncthreads();

    // Each warp normalizes 4 vocab rows.
    #pragma unroll
    for (int r = 0; r < 4; r++) {
        const int v = wid * 4 + r;
        // lane l sums j = l, l+32, l+64, l+96  (stride-33 smem: conflict-free)
        float s = 0.f;
        #pragma unroll
        for (int k = 0; k < 4; k++) {
            float e = tile[lane + 32 * k][v];
            s += e * e;
        }
        #pragma unroll
        for (int o = 16; o > 0; o >>= 1)
            s += __shfl_xor_sync(0xFFFFFFFFu, s, o);

        const float inv = 1.0f / fmaxf(sqrtf(s), 1e-12f);

        float* dst = g_table + (size_t)(v0 + v) * EMB;
        #pragma unroll
        for (int k = 0; k < 4; k++)
            dst[lane + 32 * k] = tile[lane + 32 * k][v] * inv;   // normal store: allocate in L2
    }
}

// ---------------------------------------------------------------------------
// Kernel 2: pure gather-copy. Warp handles TOK_PER_WARP tokens; lane l moves
// float4 #l of each row (warp = 512B coalesced per token). All loads are
// front-batched (MLP = TOK_PER_WARP); stores use evict-first (.cs) so the
// output stream doesn't evict the table from L2.
// ---------------------------------------------------------------------------
#define TOK_PER_WARP 8

__global__ __launch_bounds__(256) void gather_kernel(
        const int* __restrict__ x,
        float* __restrict__ out,
        int n_tok) {
    const int gwarp = (blockIdx.x * blockDim.x + threadIdx.x) >> 5;
    const int lane  = threadIdx.x & 31;
    const int t0    = gwarp * TOK_PER_WARP;
    if (t0 >= n_tok) return;

    if (t0 + TOK_PER_WARP <= n_tok) {
        int idx[TOK_PER_WARP];
        #pragma unroll
        for (int r = 0; r < TOK_PER_WARP; r++)
            idx[r] = __ldg(&x[t0 + r]);

        float4 v[TOK_PER_WARP];
        #pragma unroll
        for (int r = 0; r < TOK_PER_WARP; r++)
            v[r] = __ldg(reinterpret_cast<const float4*>(
                       g_table + (size_t)idx[r] * EMB) + lane);

        #pragma unroll
        for (int r = 0; r < TOK_PER_WARP; r++)
            __stcs(reinterpret_cast<float4*>(out + (size_t)(t0 + r) * EMB) + lane,
                   v[r]);
    } else {
        for (int t = t0; t < n_tok; t++) {
            float4 v = __ldg(reinterpret_cast<const float4*>(
                           g_table + (size_t)__ldg(&x[t]) * EMB) + lane);
            __stcs(reinterpret_cast<float4*>(out + (size_t)t * EMB) + lane, v);
        }
    }
}

// ---------------------------------------------------------------------------
extern "C" void kernel_launch(void* const* d_in, const int* in_sizes, int n_in,
                              void* d_out, int out_size) {
    const int*   x = (const int*)d_in[0];    // [4096, 200] int32
    const float* W = (const float*)d_in[1];  // [128, 100000] fp32
    const float* b = (const float*)d_in[2];  // [128] fp32
    float* out = (float*)d_out;              // [4096, 200, 128] fp32

    const int n_tok = in_sizes[0];           // 819200

    build_table_kernel<<<VOCAB / 32, 256>>>(W, b);

    const int warps_needed = (n_tok + TOK_PER_WARP - 1) / TOK_PER_WARP;
    const int blocks = (warps_needed + 7) / 8;   // 8 warps per 256-thread block
    gather_kernel<<<blocks, 256>>>(x, out, n_tok);
}

// round 3
// speedup vs baseline: 1.8966x; 1.1471x over previous
#include <cuda_runtime.h>
#include <cuda_fp16.h>
#include <cstdint>

#define VOCAB 100000
#define EMB   128

// Scratch: vocab-major, bias-fused, L2-normalized table in FP16.
// 100000 * 128 * 2B = 25.6 MB — firmly resident in GB300's ~126 MB L2.
__device__ __half g_table[(size_t)VOCAB * EMB];

// ---------------------------------------------------------------------------
// Kernel 1: table[v][:] = (half) normalize(W[:, v] + b)
// One block per 32 vocab entries. Block = 256 threads.
// ---------------------------------------------------------------------------
__global__ __launch_bounds__(256) void build_table_kernel(
        const float* __restrict__ W,
        const float* __restrict__ b) {
    __shared__ float tile[EMB][33];   // [j][v_local], pad -> conflict-free reduce

    const int v0   = blockIdx.x * 32;
    const int tid  = threadIdx.x;
    const int lane = tid & 31;
    const int wid  = tid >> 5;        // 0..7

    // Load + bias: warp reads one j-row of 32 consecutive vocab cols (128B line).
    #pragma unroll
    for (int k = 0; k < 16; k++) {
        int j = k * 8 + wid;
        tile[j][lane] = W[(size_t)j * VOCAB + v0 + lane] + b[j];
    }
    __syncthreads();

    // Each warp normalizes 4 vocab rows and writes them as half2.
    #pragma unroll
    for (int r = 0; r < 4; r++) {
        const int v = wid * 4 + r;

        float s = 0.f;
        #pragma unroll
        for (int k = 0; k < 4; k++) {
            float e = tile[lane + 32 * k][v];
            s += e * e;
        }
        #pragma unroll
        for (int o = 16; o > 0; o >>= 1)
            s += __shfl_xor_sync(0xFFFFFFFFu, s, o);

        const float inv = 1.0f / fmaxf(sqrtf(s), 1e-12f);

        __half2* dst = reinterpret_cast<__half2*>(g_table + (size_t)(v0 + v) * EMB);
        // lane writes half2 pairs (2l, 2l+1) and (64+2l, 64+2l+1): coalesced 128B + 128B
        dst[lane] = __floats2half2_rn(tile[2 * lane][v] * inv,
                                      tile[2 * lane + 1][v] * inv);
        dst[lane + 32] = __floats2half2_rn(tile[64 + 2 * lane][v] * inv,
                                           tile[64 + 2 * lane + 1][v] * inv);
    }
}

// ---------------------------------------------------------------------------
// Kernel 2: gather-copy + fp16->fp32 widen. Warp handles TOK_PER_WARP tokens;
// lane l loads uint2 (4 halves) #l of the row (warp = 256B coalesced read),
// widens to float4, stores 512B coalesced with evict-first so the output
// stream doesn't evict the table from L2.
// ---------------------------------------------------------------------------
#define TOK_PER_WARP 8

__global__ __launch_bounds__(256) void gather_kernel(
        const int* __restrict__ x,
        float* __restrict__ out,
        int n_tok) {
    const int gwarp = (blockIdx.x * blockDim.x + threadIdx.x) >> 5;
    const int lane  = threadIdx.x & 31;
    const int t0    = gwarp * TOK_PER_WARP;
    if (t0 >= n_tok) return;

    if (t0 + TOK_PER_WARP <= n_tok) {
        int idx[TOK_PER_WARP];
        #pragma unroll
        for (int r = 0; r < TOK_PER_WARP; r++)
            idx[r] = __ldg(&x[t0 + r]);

        uint2 h[TOK_PER_WARP];
        #pragma unroll
        for (int r = 0; r < TOK_PER_WARP; r++)
            h[r] = __ldg(reinterpret_cast<const uint2*>(
                       g_table + (size_t)idx[r] * EMB) + lane);

        #pragma unroll
        for (int r = 0; r < TOK_PER_WARP; r++) {
            float2 f0 = __half22float2(*reinterpret_cast<__half2*>(&h[r].x));
            float2 f1 = __half22float2(*reinterpret_cast<__half2*>(&h[r].y));
            float4 o;
            o.x = f0.x; o.y = f0.y; o.z = f1.x; o.w = f1.y;
            __stcs(reinterpret_cast<float4*>(out + (size_t)(t0 + r) * EMB) + lane, o);
        }
    } else {
        for (int t = t0; t < n_tok; t++) {
            uint2 h = __ldg(reinterpret_cast<const uint2*>(
                          g_table + (size_t)__ldg(&x[t]) * EMB) + lane);
            float2 f0 = __half22float2(*reinterpret_cast<__half2*>(&h.x));
            float2 f1 = __half22float2(*reinterpret_cast<__half2*>(&h.y));
            float4 o;
            o.x = f0.x; o.y = f0.y; o.z = f1.x; o.w = f1.y;
            __stcs(reinterpret_cast<float4*>(out + (size_t)t * EMB) + lane, o);
        }
    }
}

// ---------------------------------------------------------------------------
extern "C" void kernel_launch(void* const* d_in, const int* in_sizes, int n_in,
                              void* d_out, int out_size) {
    const int*   x = (const int*)d_in[0];    // [4096, 200] int32
    const float* W = (const float*)d_in[1];  // [128, 100000] fp32
    const float* b = (const float*)d_in[2];  // [128] fp32
    float* out = (float*)d_out;              // [4096, 200, 128] fp32

    const int n_tok = in_sizes[0];           // 819200

    build_table_kernel<<<VOCAB / 32, 256>>>(W, b);

    const int warps_needed = (n_tok + TOK_PER_WARP - 1) / TOK_PER_WARP;
    const int blocks = (warps_needed + 7) / 8;   // 8 warps per 256-thread block
    gather_kernel<<<blocks, 256>>>(x, out, n_tok);
}